// round 5
// baseline (speedup 1.0000x reference)
#include <cuda_runtime.h>
#include <cuda_bf16.h>

// Problem constants: b=1, h=w=64, s=5, H=W=1024, ps=32, q=8
#define GRID_T   64
#define NTILES   (GRID_T * GRID_T)      // 4096
#define NSTROKE  5
#define IMG      1024
#define PLANE    (IMG * IMG)            // 1048576

// Scratch (allocation-free rule: __device__ globals)
__device__ int    g_cnt[NTILES];
__device__ float4 g_sA[NTILES * NSTROKE];   // (C, S, U0, V0)   [scaled by 25]
__device__ float4 g_sB[NTILES * NSTROKE];   // (W, H, dS, dC)   [scaled by 25]
__device__ float4 g_sC[NTILES * NSTROKE];   // (cr, cg, cb, -)

__device__ __forceinline__ float tanh_(float x) {
    float r; asm("tanh.approx.f32 %0,%1;" : "=f"(r) : "f"(x)); return r;
}

// ---------------------------------------------------------------------------
// Kernel 1: per-STROKE preprocessing, order-preserving compaction of dec==1.
// sigmoid(50*(hw-|u|)) = 0.5*(1+tanh(25*(hw-|u|))) -> fold 25 into coeffs.
// ---------------------------------------------------------------------------
__global__ void prep_kernel(const float* __restrict__ param,
                            const int*   __restrict__ decision) {
    int n = blockIdx.x * blockDim.x + threadIdx.x;
    if (n >= NTILES * NSTROKE) return;
    int t = n / NSTROKE;
    int i = n - t * NSTROKE;

    int d[NSTROKE];
    #pragma unroll
    for (int j = 0; j < NSTROKE; j++) d[j] = decision[t * NSTROKE + j];
    if (i == 0) {
        int cnt = 0;
        #pragma unroll
        for (int j = 0; j < NSTROKE; j++) cnt += (d[j] != 0);
        g_cnt[t] = cnt;
    }
    if (d[i] == 0) return;
    int pos = 0;
    #pragma unroll
    for (int j = 0; j < NSTROKE; j++) pos += (j < i) && (d[j] != 0);

    const float* q = param + (size_t)n * 12;
    float p[8];
    #pragma unroll
    for (int k = 0; k < 8; k++)
        p[k] = 1.0f / (1.0f + expf(-q[k]));     // jax.nn.sigmoid

    float x0 = p[0], y0 = p[1];
    float W = 12.5f * fmaxf(p[2], 0.01f);       // 25 * (wd/2)
    float H = 12.5f * fmaxf(p[3], 0.01f);
    float th = p[4] * 3.14159265358979323846f;
    float st, ct;
    sincosf(th, &st, &ct);

    float C  = 25.0f * ct, S = 25.0f * st;
    float U0 = -(x0 * C + y0 * S);
    float V0 =  (x0 * S - y0 * C);

    int o = t * NSTROKE + pos;
    g_sA[o] = make_float4(C, S, U0, V0);
    g_sB[o] = make_float4(W, H, 0.125f * S, 0.125f * C);
    g_sC[o] = make_float4(p[5], p[6], p[7], 0.f);
}

// ---------------------------------------------------------------------------
// Kernel 2: 128-thread block = two vertically adjacent 16x16 padded cells
// (cell rows 2*by and 2*by+1). Warps 0/1 stage cell 0, warps 2/3 render it
// (warp->cell mapping is pure, no intra-warp divergence). Staging performs
// conservative per-cell culling:
//   skip entry  if alpha < ~8e-7 over whole cell
//   full cover  if alpha > 1-2e-6 over whole cell -> drop all earlier entries
//               and start the cell from that stroke's color (no canvas read).
// Each thread renders 4 pixels (rows ty+{0,4,8,12}); u/v advance by
// precomputed increments across rows.
// ---------------------------------------------------------------------------
__global__ void __launch_bounds__(128)
render_kernel(const float* __restrict__ canvas,
              float*       __restrict__ out) {
    __shared__ float4 sA[2][4 * NSTROKE];
    __shared__ float4 sB[2][4 * NSTROKE];
    __shared__ float4 sC[2][4 * NSTROKE];
    __shared__ float4 sBase[2];
    __shared__ int    sTot[2];

    const int by = blockIdx.y;           // cell rows 2*by, 2*by+1
    const int b  = blockIdx.x;           // cell col (0..64)
    const int tid  = threadIdx.y * 16 + threadIdx.x;
    const int lane = tid & 31;
    const int sw   = tid >> 5;           // warp id 0..3

    // --- staging: warp sw (<2) handles cell sw; lane = entry (p,i) ---
    if (sw < 2) {
        const int a = 2 * by + sw;
        const int p = lane / NSTROKE;    // pass 0..3 (lane<20)
        const int i = lane - p * NSTROKE;
        bool keep = false, full = false;
        float4 A, Bv, Cc;
        float U0p = 0.f, V0p = 0.f;
        if (lane < 4 * NSTROKE) {
            const int PR[4] = {0, 1, 1, 0};
            const int PC[4] = {0, 1, 0, 1};
            int r = (((a - 1) & 1) == PR[p]) ? (a - 1) : a;
            int c = (((b - 1) & 1) == PC[p]) ? (b - 1) : b;
            if ((unsigned)r < 64u && (unsigned)c < 64u) {
                int t = r * GRID_T + c;
                if (i < g_cnt[t]) {
                    int o = t * NSTROKE + i;
                    A = g_sA[o]; Bv = g_sB[o]; Cc = g_sC[o];
                    float ox = ((float)(16 * (b - c)) + 0.5f) * 0.03125f;
                    float oy = ((float)(16 * (a - r)) + 0.5f) * 0.03125f;
                    U0p = fmaf(ox, A.x, fmaf(oy, A.y, A.z));
                    V0p = fmaf(oy, A.x, fmaf(-ox, A.y, A.w));
                    // cell-local coords gx,gy in [0, 15/32]; center 7.5/32
                    float uc  = fmaf(0.234375f, A.x + A.y, U0p);
                    float vc  = fmaf(0.234375f, A.x - A.y, V0p);
                    float dev = 0.234375f * (fabsf(A.x) + fabsf(A.y));
                    float au = fabsf(uc), av = fabsf(vc);
                    bool skip = (Bv.x - au + dev < -7.f) ||
                                (Bv.y - av + dev < -7.f);
                    full = (Bv.x - au - dev > 7.f) &&
                           (Bv.y - av - dev > 7.f);
                    keep = !skip;
                }
            }
        }
        unsigned mk = __ballot_sync(0xffffffffu, keep);
        unsigned mf = __ballot_sync(0xffffffffu, keep && full);
        unsigned proc = mk;
        if (mf) {
            int lf = 31 - __clz(mf);                 // last full-cover entry
            proc = mk & ~((2u << lf) - 1u);          // keep strictly-after
            if (lane == lf) sBase[sw] = make_float4(Cc.x, Cc.y, Cc.z, 1.f);
        } else if (lane == 0) {
            sBase[sw].w = 0.f;
        }
        if (proc & (1u << lane)) {
            int pos = __popc(proc & ((1u << lane) - 1u));
            sA[sw][pos] = make_float4(A.x, A.y, U0p, V0p);
            sB[sw][pos] = Bv;
            sC[sw][pos] = Cc;
        }
        if (lane == 0) sTot[sw] = __popc(proc);
    }
    __syncthreads();

    // --- render: thread (tx, tyr); cell = tyr>>2, 4 rows ty+{0,4,8,12} ---
    const int tx   = threadIdx.x;        // 0..15
    const int tyr  = threadIdx.y;        // 0..7
    const int cell = tyr >> 2;
    const int ty   = tyr & 3;
    const int a    = 2 * by + cell;

    const int x  = 16 * b + tx - 8;      // q = 8
    const int y0 = 16 * a + ty - 8;
    const bool vx = (unsigned)x < (unsigned)IMG;

    const float4 base = sBase[cell];
    const int    tot  = sTot[cell];

    float r[4], g[4], bl[4];
    int   idx[4];
    bool  vv[4];
    #pragma unroll
    for (int k = 0; k < 4; k++) {
        int y = y0 + 4 * k;
        idx[k] = y * IMG + x;
        vv[k]  = vx && ((unsigned)y < (unsigned)IMG);
    }
    if (base.w > 0.f) {
        #pragma unroll
        for (int k = 0; k < 4; k++) { r[k] = base.x; g[k] = base.y; bl[k] = base.z; }
    } else {
        #pragma unroll
        for (int k = 0; k < 4; k++) {
            r[k] = g[k] = bl[k] = 0.f;
            if (vv[k]) {
                r[k]  = canvas[idx[k]];
                g[k]  = canvas[PLANE + idx[k]];
                bl[k] = canvas[2 * PLANE + idx[k]];
            }
        }
    }

    const float gx = (float)tx * 0.03125f;
    const float gy = (float)ty * 0.03125f;

    for (int e = 0; e < tot; e++) {            // order matters: sequential blend
        float4 A  = sA[cell][e];
        float4 B  = sB[cell][e];
        float4 Cc = sC[cell][e];

        float u = fmaf(gx, A.x, fmaf(gy, A.y, A.z));
        float v = fmaf(gy, A.x, fmaf(-gx, A.y, A.w));

        #pragma unroll
        for (int k = 0; k < 4; k++) {
            float t1 = tanh_(B.x - fabsf(u));
            float t2 = tanh_(B.y - fabsf(v));
            float al = fmaf(t1, 0.5f, 0.5f) * fmaf(t2, 0.5f, 0.5f);
            r[k]  = fmaf(al, Cc.x - r[k],  r[k]);
            g[k]  = fmaf(al, Cc.y - g[k],  g[k]);
            bl[k] = fmaf(al, Cc.z - bl[k], bl[k]);
            u += B.z;                           // +4 rows: du = 0.125*S
            v += B.w;                           //          dv = 0.125*C
        }
    }

    #pragma unroll
    for (int k = 0; k < 4; k++) {
        if (vv[k]) {
            out[idx[k]]             = r[k];
            out[PLANE + idx[k]]     = g[k];
            out[2 * PLANE + idx[k]] = bl[k];
        }
    }
}

// ---------------------------------------------------------------------------
extern "C" void kernel_launch(void* const* d_in, const int* in_sizes, int n_in,
                              void* d_out, int out_size) {
    const float* param    = (const float*)d_in[0];   // (1,64,64,5,12) f32
    const int*   decision = (const int*)  d_in[1];   // (1,64,64,5)    i32
    const float* canvas   = (const float*)d_in[2];   // (1,3,1024,1024) f32
    float*       out      = (float*)d_out;           // (1,3,1024,1024) f32

    prep_kernel<<<(NTILES * NSTROKE + 255) / 256, 256>>>(param, decision);

    dim3 bs(16, 8);          // 128 threads, two cells per block, 4 px/thread
    dim3 gs(65, 33);         // 65 x 66 cells (row 65 auto-invalid)
    render_kernel<<<gs, bs>>>(canvas, out);
}